// round 5
// baseline (speedup 1.0000x reference)
#include <cuda_runtime.h>
#include <cstdint>

#define N_NODES 100000
#define D 128
#define N_EDGES 1000000
#define M_TILE 128
#define NUM_TILES ((N_NODES + M_TILE - 1) / M_TILE)   // 782

// Scratch (no allocation allowed -> __device__ globals)
__device__ alignas(16) float g_agg[(size_t)N_NODES * D];
__device__ alignas(16) float g_h1 [(size_t)N_NODES * D];
__device__ int g_deg[N_NODES];
__device__ int g_rowptr[N_NODES + 1];
__device__ int g_cursor[N_NODES];
__device__ int g_esrc[N_EDGES];

// ---------------------------------------------------------------------------
// CSR construction (graph identical for both layers -> build once)
// ---------------------------------------------------------------------------
__global__ void zero_deg_kernel() {
    int i = blockIdx.x * blockDim.x + threadIdx.x;
    if (i < N_NODES) g_deg[i] = 0;
}

__global__ void count_kernel(const int* __restrict__ ei) {
    int i = blockIdx.x * blockDim.x + threadIdx.x;
    int stride = gridDim.x * blockDim.x;
    for (; i < N_EDGES; i += stride) {
        int d = ei[N_EDGES + i];
        d = min(max(d, 0), N_NODES - 1);
        atomicAdd(&g_deg[d], 1);
    }
}

// Single-block exclusive scan: g_deg -> g_rowptr / g_cursor
__global__ void __launch_bounds__(1024, 1) scan_kernel() {
    __shared__ int part[1024];
    const int t = threadIdx.x;
    const int R = (N_NODES + 1023) / 1024;      // 98
    int beg = t * R;
    int end = min(beg + R, N_NODES);
    int s = 0;
    for (int i = beg; i < end; i++) s += g_deg[i];
    part[t] = s;
    __syncthreads();
    // Hillis-Steele inclusive scan
    for (int off = 1; off < 1024; off <<= 1) {
        int v = (t >= off) ? part[t - off] : 0;
        __syncthreads();
        part[t] += v;
        __syncthreads();
    }
    int base = (t == 0) ? 0 : part[t - 1];
    for (int i = beg; i < end; i++) {
        g_rowptr[i] = base;
        g_cursor[i] = base;
        base += g_deg[i];
    }
    if (t == 1023) g_rowptr[N_NODES] = part[1023];
}

__global__ void fill_kernel(const int* __restrict__ ei) {
    int i = blockIdx.x * blockDim.x + threadIdx.x;
    int stride = gridDim.x * blockDim.x;
    for (; i < N_EDGES; i += stride) {
        int s = ei[i];
        int d = ei[N_EDGES + i];
        s = min(max(s, 0), N_NODES - 1);
        d = min(max(d, 0), N_NODES - 1);
        int pos = atomicAdd(&g_cursor[d], 1);
        g_esrc[pos] = s;
    }
}

// ---------------------------------------------------------------------------
// Pull aggregation: one warp per dst node; lane l owns float4 column l.
// Register accumulation, single write of the mean. No atomics, no zeroing.
// ---------------------------------------------------------------------------
__global__ void aggregate_kernel(const float* __restrict__ x) {
    int gt = blockIdx.x * blockDim.x + threadIdx.x;
    int lane = gt & 31;
    int warp = gt >> 5;
    int nwarps = (gridDim.x * blockDim.x) >> 5;
    for (int n = warp; n < N_NODES; n += nwarps) {
        int beg = g_rowptr[n];
        int end = g_rowptr[n + 1];
        float4 acc = make_float4(0.f, 0.f, 0.f, 0.f);
        for (int eb = beg; eb < end; eb += 32) {
            int cnt = min(end - eb, 32);
            int sv = (lane < cnt) ? g_esrc[eb + lane] : 0;
            for (int j = 0; j < cnt; j++) {
                int s = __shfl_sync(0xFFFFFFFFu, sv, j);
                float4 v = ((const float4*)(x + (size_t)s * D))[lane];
                acc.x += v.x; acc.y += v.y; acc.z += v.z; acc.w += v.w;
            }
        }
        float sc = 1.f / (float)max(end - beg, 1);
        acc.x *= sc; acc.y *= sc; acc.z *= sc; acc.w *= sc;
        ((float4*)(g_agg + (size_t)n * D))[lane] = acc;
    }
}

// ---------------------------------------------------------------------------
// Tensor-core fused SAGE GEMM via mma.sync tf32 (m16n8k8) — sm_100-legal.
//   out[m,:] = act( agg[m,:] @ Wl + x[m,:] @ Wr + b )   (agg pre-scaled)
// One GEMM: A' = [agg | x] (K=256), B = W'^T staged [K=256][N=128].
// Block: 512 threads = 16 warps in a 4x4 grid; warp tile 32(m) x 32(n).
// SMEM strides chosen for conflict-free mma-fragment LDS.
// ---------------------------------------------------------------------------
#define SB 136
#define SA 68
#define WS_WORDS (256 * SB)                    // 34816
#define SMEM_WORDS (WS_WORDS + 128 * SA)       // 43520
#define GEMM_SMEM_BYTES (SMEM_WORDS * 4)       // 174080

__device__ __forceinline__ uint32_t f2tf32(float v) {
    uint32_t r;
    asm("cvt.rna.tf32.f32 %0, %1;" : "=r"(r) : "f"(v));
    return r;
}

__global__ void __launch_bounds__(512, 1)
sage_gemm_mma(const float* __restrict__ x,
              const float* __restrict__ wl,
              const float* __restrict__ wr,
              const float* __restrict__ bias,
              float* __restrict__ out,
              int do_relu) {
    extern __shared__ float sm[];
    float* wS = sm;              // [256][SB]
    float* aS = sm + WS_WORDS;   // [128][SA]

    const int tid = threadIdx.x;
    const int wid = tid >> 5;
    const int lane = tid & 31;
    const int grp = lane >> 2;    // 0..7
    const int tig = lane & 3;     // 0..3
    const int warp_m = wid & 3;   // m offset = 32*warp_m
    const int warp_n = wid >> 2;  // n offset = 32*warp_n

    // ---- Stage B = W'^T once: wS[k][n] = tf32(k<128 ? wl[k][n] : wr[k-128][n])
    for (int i = tid; i < 256 * 128; i += 512) {
        int k = i >> 7, n = i & 127;
        float v = (k < 128) ? wl[k * 128 + n] : wr[(k - 128) * 128 + n];
        wS[k * SB + n] = __uint_as_float(f2tf32(v));
    }

    for (int t = blockIdx.x; t < NUM_TILES; t += gridDim.x) {
        const int m_base = t * M_TILE;
        float acc[32];
#pragma unroll
        for (int i = 0; i < 32; i++) acc[i] = 0.f;

        for (int chunk = 0; chunk < 4; chunk++) {
            __syncthreads();  // previous aS consumers done (also fences wS stage)
            // ---- Stage A chunk [128 m][64 k], tf32-converted ----
            for (int i = tid; i < 2048; i += 512) {
                int m = i >> 4;
                int kq = i & 15;
                int gm = m_base + m;
                int kg = chunk * 64 + (kq << 2);
                float4 v = make_float4(0.f, 0.f, 0.f, 0.f);
                if (gm < N_NODES) {
                    if (kg < 128)
                        v = *(const float4*)(g_agg + (size_t)gm * D + kg);
                    else
                        v = *(const float4*)(x + (size_t)gm * D + (kg - 128));
                }
                float4 c;
                c.x = __uint_as_float(f2tf32(v.x));
                c.y = __uint_as_float(f2tf32(v.y));
                c.z = __uint_as_float(f2tf32(v.z));
                c.w = __uint_as_float(f2tf32(v.w));
                *(float4*)&aS[m * SA + (kq << 2)] = c;
            }
            __syncthreads();

            // ---- Compute: 8 k-atoms of K=8 ----
#pragma unroll
            for (int ka = 0; ka < 8; ka++) {
                const int kc = ka * 8;
                const int kw = chunk * 64 + kc;
                uint32_t bfr[8];
#pragma unroll
                for (int j = 0; j < 4; j++) {
                    int nb = warp_n * 32 + j * 8 + grp;
                    bfr[j * 2]     = __float_as_uint(wS[(kw + tig) * SB + nb]);
                    bfr[j * 2 + 1] = __float_as_uint(wS[(kw + tig + 4) * SB + nb]);
                }
                uint32_t afr[8];
#pragma unroll
                for (int i = 0; i < 2; i++) {
                    int mb = warp_m * 32 + i * 16;
                    afr[i * 4 + 0] = __float_as_uint(aS[(mb + grp) * SA + kc + tig]);
                    afr[i * 4 + 1] = __float_as_uint(aS[(mb + grp + 8) * SA + kc + tig]);
                    afr[i * 4 + 2] = __float_as_uint(aS[(mb + grp) * SA + kc + tig + 4]);
                    afr[i * 4 + 3] = __float_as_uint(aS[(mb + grp + 8) * SA + kc + tig + 4]);
                }
#pragma unroll
                for (int i = 0; i < 2; i++)
#pragma unroll
                    for (int j = 0; j < 4; j++) {
                        float* c = &acc[(i * 4 + j) * 4];
                        asm volatile(
                            "mma.sync.aligned.m16n8k8.row.col.f32.tf32.tf32.f32 "
                            "{%0,%1,%2,%3}, {%4,%5,%6,%7}, {%8,%9}, {%0,%1,%2,%3};"
                            : "+f"(c[0]), "+f"(c[1]), "+f"(c[2]), "+f"(c[3])
                            : "r"(afr[i * 4]), "r"(afr[i * 4 + 1]),
                              "r"(afr[i * 4 + 2]), "r"(afr[i * 4 + 3]),
                              "r"(bfr[j * 2]), "r"(bfr[j * 2 + 1]));
                    }
            }
        }

        // ---- Epilogue: bias (+ReLU), store float2 per c-pair ----
#pragma unroll
        for (int j = 0; j < 4; j++) {
            int c0 = warp_n * 32 + j * 8 + 2 * tig;
            float b0 = bias[c0], b1 = bias[c0 + 1];
#pragma unroll
            for (int i = 0; i < 2; i++) {
                float* a = &acc[(i * 4 + j) * 4];
                int r0 = m_base + warp_m * 32 + i * 16 + grp;
#pragma unroll
                for (int h = 0; h < 2; h++) {
                    int r = r0 + h * 8;
                    if (r < N_NODES) {
                        float v0 = a[h * 2 + 0] + b0;
                        float v1 = a[h * 2 + 1] + b1;
                        if (do_relu) { v0 = fmaxf(v0, 0.f); v1 = fmaxf(v1, 0.f); }
                        *(float2*)(out + (size_t)r * D + c0) = make_float2(v0, v1);
                    }
                }
            }
        }
    }
}

// ---------------------------------------------------------------------------
// Launcher
// ---------------------------------------------------------------------------
extern "C" void kernel_launch(void* const* d_in, const int* in_sizes, int n_in,
                              void* d_out, int out_size) {
    const int* edge_index = (const int*)d_in[0];   // int32 (JAX default int)
    const float* node_emb = (const float*)d_in[1];
    const float* w1_l = (const float*)d_in[2];
    const float* b1_l = (const float*)d_in[3];
    const float* w1_r = (const float*)d_in[4];
    const float* w2_l = (const float*)d_in[5];
    const float* b2_l = (const float*)d_in[6];
    const float* w2_r = (const float*)d_in[7];
    float* out = (float*)d_out;

    static bool attr_set = false;
    if (!attr_set) {
        cudaFuncSetAttribute(sage_gemm_mma,
                             cudaFuncAttributeMaxDynamicSharedMemorySize,
                             GEMM_SMEM_BYTES);
        attr_set = true;
    }

    float* h1_p;   cudaGetSymbolAddress((void**)&h1_p, g_h1);

    // --- CSR build (once; graph shared by both layers) ---
    zero_deg_kernel<<<(N_NODES + 255) / 256, 256>>>();
    count_kernel<<<1024, 256>>>(edge_index);
    scan_kernel<<<1, 1024>>>();
    fill_kernel<<<1024, 256>>>(edge_index);

    // --- layer 1 ---
    aggregate_kernel<<<2048, 256>>>(node_emb);
    sage_gemm_mma<<<148, 512, GEMM_SMEM_BYTES>>>(node_emb, w1_l, w1_r, b1_l,
                                                 h1_p, 1);

    // --- layer 2 ---
    aggregate_kernel<<<2048, 256>>>(h1_p);
    sage_gemm_mma<<<148, 512, GEMM_SMEM_BYTES>>>(h1_p, w2_l, w2_r, b2_l,
                                                 out, 0);

    (void)in_sizes; (void)n_in; (void)out_size;
}

// round 6
// speedup vs baseline: 1.1165x; 1.1165x over previous
#include <cuda_runtime.h>
#include <cstdint>

#define N_NODES 100000
#define D 128
#define N_EDGES 1000000
#define M_TILE 128
#define NUM_TILES ((N_NODES + M_TILE - 1) / M_TILE)   // 782

// Scratch (no allocation allowed -> __device__ globals)
__device__ alignas(16) float g_agg[(size_t)N_NODES * D];
__device__ alignas(16) float g_h1 [(size_t)N_NODES * D];
__device__ alignas(16) float g_cnt[N_NODES];

// ---------------------------------------------------------------------------
// Zero a float buffer
// ---------------------------------------------------------------------------
__global__ void zero_kernel(float4* p, int count4) {
    int i = blockIdx.x * blockDim.x + threadIdx.x;
    int stride = gridDim.x * blockDim.x;
    float4 z = make_float4(0.f, 0.f, 0.f, 0.f);
    for (; i < count4; i += stride) p[i] = z;
}

// ---------------------------------------------------------------------------
// Scatter: one warp per edge; lane l handles float4 l of the 128-float row.
// Vector reduction (red.global.add.v4.f32). do_count: lane 0 bumps degree.
// ---------------------------------------------------------------------------
__global__ void scatter_kernel(const int* __restrict__ ei,
                               const float* __restrict__ x,
                               int do_count) {
    int gt = blockIdx.x * blockDim.x + threadIdx.x;
    int lane = gt & 31;
    int warp = gt >> 5;
    int nwarps = (gridDim.x * blockDim.x) >> 5;
    for (int e = warp; e < N_EDGES; e += nwarps) {
        int s = ei[e];
        int d = ei[N_EDGES + e];
        s = min(max(s, 0), N_NODES - 1);
        d = min(max(d, 0), N_NODES - 1);
        if (do_count && lane == 0) atomicAdd(&g_cnt[d], 1.0f);
        const float4* srcp = (const float4*)(x + (size_t)s * D);
        float4 v = srcp[lane];
        float* dst = g_agg + (size_t)d * D + lane * 4;
        asm volatile("red.global.add.v4.f32 [%0], {%1,%2,%3,%4};"
                     :: "l"(dst), "f"(v.x), "f"(v.y), "f"(v.z), "f"(v.w)
                     : "memory");
    }
}

// ---------------------------------------------------------------------------
// Tensor-core fused SAGE GEMM via mma.sync tf32 (m16n8k8) — sm_100-legal.
//   out[m,:] = act( (agg[m,:]/cnt[m]) @ Wl + x[m,:] @ Wr + b )
// A' = [agg*inv | x] (K=256), B = W'^T.
// k-pair-adjacent layouts: lane tig loads its two k-values (positions
// tig / tig+4) as a single LDS.64; A and B use the identical in-atom
// permutation, so the MMA result is unchanged.
//   wB[ka][n][kk]: word = ka*1024 + n*8 + kk      (n-stride 8, CF per half-warp)
//   aS[m][kq*4]  : word = m*72 + kq*4             (m-stride 72 ≡ 8 mod 32, CF)
// ---------------------------------------------------------------------------
#define B_WORDS (32 * 1024)              // 32 katoms * 128 n * 8 kk
#define A_STRIDE 72
#define A_WORDS (128 * A_STRIDE)         // 9216
#define GEMM_SMEM_BYTES ((B_WORDS + A_WORDS) * 4)   // 167936

__device__ __forceinline__ uint32_t f2tf32(float v) {
    uint32_t r;
    asm("cvt.rna.tf32.f32 %0, %1;" : "=r"(r) : "f"(v));
    return r;
}

__global__ void __launch_bounds__(512, 1)
sage_gemm_mma(const float* __restrict__ x,
              const float* __restrict__ wl,
              const float* __restrict__ wr,
              const float* __restrict__ bias,
              float* __restrict__ out,
              int do_relu) {
    extern __shared__ float sm[];
    float* wB = sm;              // [32 ka][128 n][8 kk]
    float* aS = sm + B_WORDS;    // [128 m][A_STRIDE]

    const int tid = threadIdx.x;
    const int wid = tid >> 5;
    const int lane = tid & 31;
    const int grp = lane >> 2;    // 0..7
    const int tig = lane & 3;     // 0..3
    const int warp_m = wid & 3;   // m offset = 32*warp_m
    const int warp_n = wid >> 2;  // n offset = 32*warp_n

    // ---- Stage B = W'^T once: wB[ka][n][kk] = tf32(W'[ka*8+kk][n]) ----
    for (int i = tid; i < 8192; i += 512) {
        int n = i & 127;
        int t2 = i >> 7;          // 0..63
        int ka = t2 >> 1;
        int h = t2 & 1;
        int kb = ka * 8 + h * 4;
        float4 v;
        v.x = (kb + 0 < 128) ? wl[(kb + 0) * 128 + n] : wr[(kb - 128 + 0) * 128 + n];
        v.y = (kb + 1 < 128) ? wl[(kb + 1) * 128 + n] : wr[(kb - 128 + 1) * 128 + n];
        v.z = (kb + 2 < 128) ? wl[(kb + 2) * 128 + n] : wr[(kb - 128 + 2) * 128 + n];
        v.w = (kb + 3 < 128) ? wl[(kb + 3) * 128 + n] : wr[(kb - 128 + 3) * 128 + n];
        float4 c;
        c.x = __uint_as_float(f2tf32(v.x));
        c.y = __uint_as_float(f2tf32(v.y));
        c.z = __uint_as_float(f2tf32(v.z));
        c.w = __uint_as_float(f2tf32(v.w));
        *(float4*)&wB[ka * 1024 + n * 8 + h * 4] = c;
    }

    for (int t = blockIdx.x; t < NUM_TILES; t += gridDim.x) {
        const int m_base = t * M_TILE;
        float acc[32];
#pragma unroll
        for (int i = 0; i < 32; i++) acc[i] = 0.f;

        for (int chunk = 0; chunk < 4; chunk++) {
            __syncthreads();  // previous aS consumers done (also fences wB stage)
            // ---- Stage A chunk [128 m][64 k] ----
            for (int i = tid; i < 2048; i += 512) {
                int m = i >> 4;
                int kq = i & 15;
                int gm = m_base + m;
                int kg = chunk * 64 + (kq << 2);
                float4 v = make_float4(0.f, 0.f, 0.f, 0.f);
                if (gm < N_NODES) {
                    if (kg < 128) {
                        v = *(const float4*)(g_agg + (size_t)gm * D + kg);
                        float s = __frcp_rn(fmaxf(g_cnt[gm], 1.0f));
                        v.x *= s; v.y *= s; v.z *= s; v.w *= s;
                    } else {
                        v = *(const float4*)(x + (size_t)gm * D + (kg - 128));
                    }
                }
                float4 c;
                c.x = __uint_as_float(f2tf32(v.x));
                c.y = __uint_as_float(f2tf32(v.y));
                c.z = __uint_as_float(f2tf32(v.z));
                c.w = __uint_as_float(f2tf32(v.w));
                *(float4*)&aS[m * A_STRIDE + (kq << 2)] = c;
            }
            __syncthreads();

            // ---- Compute: 8 k-atoms of K=8, LDS.64 fragment loads ----
#pragma unroll
            for (int ka = 0; ka < 8; ka++) {
                const int kag = chunk * 8 + ka;
                float2 bf[4];
#pragma unroll
                for (int j = 0; j < 4; j++) {
                    int nb = warp_n * 32 + j * 8 + grp;
                    bf[j] = *(float2*)&wB[kag * 1024 + nb * 8 + 2 * tig];
                }
                float2 alo[2], ahi[2];
#pragma unroll
                for (int i = 0; i < 2; i++) {
                    int mb = warp_m * 32 + i * 16;
                    alo[i] = *(float2*)&aS[(mb + grp) * A_STRIDE + ka * 8 + 2 * tig];
                    ahi[i] = *(float2*)&aS[(mb + grp + 8) * A_STRIDE + ka * 8 + 2 * tig];
                }
#pragma unroll
                for (int i = 0; i < 2; i++)
#pragma unroll
                    for (int j = 0; j < 4; j++) {
                        float* c = &acc[(i * 4 + j) * 4];
                        asm volatile(
                            "mma.sync.aligned.m16n8k8.row.col.f32.tf32.tf32.f32 "
                            "{%0,%1,%2,%3}, {%4,%5,%6,%7}, {%8,%9}, {%0,%1,%2,%3};"
                            : "+f"(c[0]), "+f"(c[1]), "+f"(c[2]), "+f"(c[3])
                            : "r"(__float_as_uint(alo[i].x)),
                              "r"(__float_as_uint(ahi[i].x)),
                              "r"(__float_as_uint(alo[i].y)),
                              "r"(__float_as_uint(ahi[i].y)),
                              "r"(__float_as_uint(bf[j].x)),
                              "r"(__float_as_uint(bf[j].y)));
                    }
            }
        }

        // ---- Epilogue: bias (+ReLU), store float2 per c-pair ----
#pragma unroll
        for (int j = 0; j < 4; j++) {
            int c0 = warp_n * 32 + j * 8 + 2 * tig;
            float b0 = bias[c0], b1 = bias[c0 + 1];
#pragma unroll
            for (int i = 0; i < 2; i++) {
                float* a = &acc[(i * 4 + j) * 4];
                int r0 = m_base + warp_m * 32 + i * 16 + grp;
#pragma unroll
                for (int h = 0; h < 2; h++) {
                    int r = r0 + h * 8;
                    if (r < N_NODES) {
                        float v0 = a[h * 2 + 0] + b0;
                        float v1 = a[h * 2 + 1] + b1;
                        if (do_relu) { v0 = fmaxf(v0, 0.f); v1 = fmaxf(v1, 0.f); }
                        *(float2*)(out + (size_t)r * D + c0) = make_float2(v0, v1);
                    }
                }
            }
        }
    }
}

// ---------------------------------------------------------------------------
// Launcher
// ---------------------------------------------------------------------------
extern "C" void kernel_launch(void* const* d_in, const int* in_sizes, int n_in,
                              void* d_out, int out_size) {
    const int* edge_index = (const int*)d_in[0];   // int32 (JAX default int)
    const float* node_emb = (const float*)d_in[1];
    const float* w1_l = (const float*)d_in[2];
    const float* b1_l = (const float*)d_in[3];
    const float* w1_r = (const float*)d_in[4];
    const float* w2_l = (const float*)d_in[5];
    const float* b2_l = (const float*)d_in[6];
    const float* w2_r = (const float*)d_in[7];
    float* out = (float*)d_out;

    static bool attr_set = false;
    if (!attr_set) {
        cudaFuncSetAttribute(sage_gemm_mma,
                             cudaFuncAttributeMaxDynamicSharedMemorySize,
                             GEMM_SMEM_BYTES);
        attr_set = true;
    }

    float* agg_p;  cudaGetSymbolAddress((void**)&agg_p, g_agg);
    float* cnt_p;  cudaGetSymbolAddress((void**)&cnt_p, g_cnt);
    float* h1_p;   cudaGetSymbolAddress((void**)&h1_p, g_h1);

    const int agg4 = N_NODES * D / 4;

    // zero counts + layer-1 accumulator
    zero_kernel<<<64, 256>>>((float4*)cnt_p, N_NODES / 4);
    zero_kernel<<<2048, 256>>>((float4*)agg_p, agg4);

    // --- layer 1 ---
    scatter_kernel<<<2048, 256>>>(edge_index, node_emb, 1);
    sage_gemm_mma<<<148, 512, GEMM_SMEM_BYTES>>>(node_emb, w1_l, w1_r, b1_l,
                                                 h1_p, 1);

    // --- layer 2 ---
    zero_kernel<<<2048, 256>>>((float4*)agg_p, agg4);
    scatter_kernel<<<2048, 256>>>(edge_index, h1_p, 0);
    sage_gemm_mma<<<148, 512, GEMM_SMEM_BYTES>>>(h1_p, w2_l, w2_r, b2_l,
                                                 out, 0);

    (void)in_sizes; (void)n_in; (void)out_size;
}

// round 8
// speedup vs baseline: 1.2842x; 1.1502x over previous
#include <cuda_runtime.h>
#include <cstdint>

#define N_NODES 100000
#define D 128
#define N_EDGES 1000000
#define M_TILE 128
#define NUM_TILES ((N_NODES + M_TILE - 1) / M_TILE)   // 782

// Scratch (no allocation allowed -> __device__ globals)
__device__ alignas(16) float g_agg[(size_t)N_NODES * D];
__device__ alignas(16) float g_h1 [(size_t)N_NODES * D];
__device__ alignas(16) float g_cnt[N_NODES];

// ---------------------------------------------------------------------------
// Zero a float buffer
// ---------------------------------------------------------------------------
__global__ void zero_kernel(float4* p, int count4) {
    int i = blockIdx.x * blockDim.x + threadIdx.x;
    int stride = gridDim.x * blockDim.x;
    float4 z = make_float4(0.f, 0.f, 0.f, 0.f);
    for (; i < count4; i += stride) p[i] = z;
}

// ---------------------------------------------------------------------------
// Scatter: one warp per edge; lane l handles float4 l of the 128-float row.
// Vector reduction (red.global.add.v4.f32). do_count: lane 0 bumps degree.
// ---------------------------------------------------------------------------
__global__ void scatter_kernel(const int* __restrict__ ei,
                               const float* __restrict__ x,
                               int do_count) {
    int gt = blockIdx.x * blockDim.x + threadIdx.x;
    int lane = gt & 31;
    int warp = gt >> 5;
    int nwarps = (gridDim.x * blockDim.x) >> 5;
    for (int e = warp; e < N_EDGES; e += nwarps) {
        int s = ei[e];
        int d = ei[N_EDGES + e];
        s = min(max(s, 0), N_NODES - 1);
        d = min(max(d, 0), N_NODES - 1);
        if (do_count && lane == 0) atomicAdd(&g_cnt[d], 1.0f);
        const float4* srcp = (const float4*)(x + (size_t)s * D);
        float4 v = srcp[lane];
        float* dst = g_agg + (size_t)d * D + lane * 4;
        asm volatile("red.global.add.v4.f32 [%0], {%1,%2,%3,%4};"
                     :: "l"(dst), "f"(v.x), "f"(v.y), "f"(v.z), "f"(v.w)
                     : "memory");
    }
}

// ---------------------------------------------------------------------------
// Tensor-core fused SAGE GEMM via mma.sync tf32 (m16n8k8) — sm_100-legal.
//   out[m,:] = act( (agg[m,:]/cnt[m]) @ Wl + x[m,:] @ Wr + b )
// A' = [agg*inv | x] (K=256), B = W'^T.
// Software pipeline: double-buffered A tile; each thread prefetches the next
// chunk's 4 float4 rows into registers BEFORE computing the current chunk
// (LDG latency hidden behind 64 MMAs/warp), stores to the alternate buffer
// after compute; ONE __syncthreads per chunk.
//   wB[ka][n][kk]: word = ka*1024 + n*8 + kk      (n-stride 8, CF per half-warp)
//   aS[m][kq*4]  : word = m*72 + kq*4             (m-stride 72 ≡ 8 mod 32, CF)
// ---------------------------------------------------------------------------
#define B_WORDS (32 * 1024)              // 32 katoms * 128 n * 8 kk
#define A_STRIDE 72
#define A_WORDS (128 * A_STRIDE)         // 9216
#define GEMM_SMEM_BYTES ((B_WORDS + 2 * A_WORDS) * 4)   // 204800

__device__ __forceinline__ uint32_t f2tf32(float v) {
    uint32_t r;
    asm("cvt.rna.tf32.f32 %0, %1;" : "=r"(r) : "f"(v));
    return r;
}

__global__ void __launch_bounds__(512, 1)
sage_gemm_mma(const float* __restrict__ x,
              const float* __restrict__ wl,
              const float* __restrict__ wr,
              const float* __restrict__ bias,
              float* __restrict__ out,
              int do_relu) {
    extern __shared__ float sm[];
    float* wB = sm;               // [32 ka][128 n][8 kk]
    float* aS0 = sm + B_WORDS;    // [128 m][A_STRIDE]  (buffer 0)
    float* aS1 = aS0 + A_WORDS;   // buffer 1

    const int tid = threadIdx.x;
    const int wid = tid >> 5;
    const int lane = tid & 31;
    const int grp = lane >> 2;    // 0..7
    const int tig = lane & 3;     // 0..3
    const int warp_m = wid & 3;   // m offset = 32*warp_m
    const int warp_n = wid >> 2;  // n offset = 32*warp_n

    // Per-thread staging coordinates (4 slots: i = tid + q*512)
    int sm_m[4], sm_kq[4];
#pragma unroll
    for (int q = 0; q < 4; q++) {
        int i = tid + q * 512;
        sm_m[q] = i >> 4;
        sm_kq[q] = i & 15;
    }

    // ---- Stage B = W'^T once: wB[ka][n][kk] = tf32(W'[ka*8+kk][n]) ----
    for (int i = tid; i < 8192; i += 512) {
        int n = i & 127;
        int t2 = i >> 7;          // 0..63
        int ka = t2 >> 1;
        int h = t2 & 1;
        int kb = ka * 8 + h * 4;
        float4 v;
        v.x = (kb + 0 < 128) ? wl[(kb + 0) * 128 + n] : wr[(kb - 128 + 0) * 128 + n];
        v.y = (kb + 1 < 128) ? wl[(kb + 1) * 128 + n] : wr[(kb - 128 + 1) * 128 + n];
        v.z = (kb + 2 < 128) ? wl[(kb + 2) * 128 + n] : wr[(kb - 128 + 2) * 128 + n];
        v.w = (kb + 3 < 128) ? wl[(kb + 3) * 128 + n] : wr[(kb - 128 + 3) * 128 + n];
        float4 c;
        c.x = __uint_as_float(f2tf32(v.x));
        c.y = __uint_as_float(f2tf32(v.y));
        c.z = __uint_as_float(f2tf32(v.z));
        c.w = __uint_as_float(f2tf32(v.w));
        *(float4*)&wB[ka * 1024 + n * 8 + h * 4] = c;
    }

    float4 rv[4];
    float cf[4];

    // prefetch loader: chunk -> registers
    auto load_chunk = [&](int m_base, int chunk) {
#pragma unroll
        for (int q = 0; q < 4; q++) {
            int gm = m_base + sm_m[q];
            rv[q] = make_float4(0.f, 0.f, 0.f, 0.f);
            cf[q] = 1.f;
            if (gm < N_NODES) {
                int kg = chunk * 64 + (sm_kq[q] << 2);
                if (chunk < 2) {
                    rv[q] = *(const float4*)(g_agg + (size_t)gm * D + kg);
                    cf[q] = g_cnt[gm];
                } else {
                    rv[q] = *(const float4*)(x + (size_t)gm * D + (kg - 128));
                }
            }
        }
    };
    // store registers -> smem buffer (tf32 convert, agg scaling)
    auto store_chunk = [&](float* buf, int chunk) {
#pragma unroll
        for (int q = 0; q < 4; q++) {
            float4 v = rv[q];
            if (chunk < 2) {
                float s = __frcp_rn(fmaxf(cf[q], 1.0f));
                v.x *= s; v.y *= s; v.z *= s; v.w *= s;
            }
            float4 c;
            c.x = __uint_as_float(f2tf32(v.x));
            c.y = __uint_as_float(f2tf32(v.y));
            c.z = __uint_as_float(f2tf32(v.z));
            c.w = __uint_as_float(f2tf32(v.w));
            *(float4*)&buf[sm_m[q] * A_STRIDE + (sm_kq[q] << 2)] = c;
        }
    };

    for (int t = blockIdx.x; t < NUM_TILES; t += gridDim.x) {
        const int m_base = t * M_TILE;
        float acc[32];
#pragma unroll
        for (int i = 0; i < 32; i++) acc[i] = 0.f;

        // prologue: stage chunk 0 into buffer 0
        load_chunk(m_base, 0);
        store_chunk(aS0, 0);
        __syncthreads();   // also fences the one-time wB stage

#pragma unroll
        for (int chunk = 0; chunk < 4; chunk++) {
            float* cur = (chunk & 1) ? aS1 : aS0;
            float* nxt = (chunk & 1) ? aS0 : aS1;

            if (chunk < 3) load_chunk(m_base, chunk + 1);  // LDG overlaps MMAs

            // ---- Compute: 8 k-atoms of K=8, LDS.64 fragment loads ----
#pragma unroll
            for (int ka = 0; ka < 8; ka++) {
                const int kag = chunk * 8 + ka;
                float2 bf[4];
#pragma unroll
                for (int j = 0; j < 4; j++) {
                    int nb = warp_n * 32 + j * 8 + grp;
                    bf[j] = *(float2*)&wB[kag * 1024 + nb * 8 + 2 * tig];
                }
                float2 alo[2], ahi[2];
#pragma unroll
                for (int i = 0; i < 2; i++) {
                    int mb = warp_m * 32 + i * 16;
                    alo[i] = *(float2*)&cur[(mb + grp) * A_STRIDE + ka * 8 + 2 * tig];
                    ahi[i] = *(float2*)&cur[(mb + grp + 8) * A_STRIDE + ka * 8 + 2 * tig];
                }
#pragma unroll
                for (int i = 0; i < 2; i++)
#pragma unroll
                    for (int j = 0; j < 4; j++) {
                        float* c = &acc[(i * 4 + j) * 4];
                        asm volatile(
                            "mma.sync.aligned.m16n8k8.row.col.f32.tf32.tf32.f32 "
                            "{%0,%1,%2,%3}, {%4,%5,%6,%7}, {%8,%9}, {%0,%1,%2,%3};"
                            : "+f"(c[0]), "+f"(c[1]), "+f"(c[2]), "+f"(c[3])
                            : "r"(__float_as_uint(alo[i].x)),
                              "r"(__float_as_uint(ahi[i].x)),
                              "r"(__float_as_uint(alo[i].y)),
                              "r"(__float_as_uint(ahi[i].y)),
                              "r"(__float_as_uint(bf[j].x)),
                              "r"(__float_as_uint(bf[j].y)));
                    }
            }

            if (chunk < 3) store_chunk(nxt, chunk + 1);
            __syncthreads();
        }

        // ---- Epilogue: bias (+ReLU), store float2 per c-pair ----
#pragma unroll
        for (int j = 0; j < 4; j++) {
            int c0 = warp_n * 32 + j * 8 + 2 * tig;
            float b0 = bias[c0], b1 = bias[c0 + 1];
#pragma unroll
            for (int i = 0; i < 2; i++) {
                float* a = &acc[(i * 4 + j) * 4];
                int r0 = m_base + warp_m * 32 + i * 16 + grp;
#pragma unroll
                for (int h = 0; h < 2; h++) {
                    int r = r0 + h * 8;
                    if (r < N_NODES) {
                        float v0 = a[h * 2 + 0] + b0;
                        float v1 = a[h * 2 + 1] + b1;
                        if (do_relu) { v0 = fmaxf(v0, 0.f); v1 = fmaxf(v1, 0.f); }
                        *(float2*)(out + (size_t)r * D + c0) = make_float2(v0, v1);
                    }
                }
            }
        }
    }
}

// ---------------------------------------------------------------------------
// Launcher
// ---------------------------------------------------------------------------
extern "C" void kernel_launch(void* const* d_in, const int* in_sizes, int n_in,
                              void* d_out, int out_size) {
    const int* edge_index = (const int*)d_in[0];   // int32 (JAX default int)
    const float* node_emb = (const float*)d_in[1];
    const float* w1_l = (const float*)d_in[2];
    const float* b1_l = (const float*)d_in[3];
    const float* w1_r = (const float*)d_in[4];
    const float* w2_l = (const float*)d_in[5];
    const float* b2_l = (const float*)d_in[6];
    const float* w2_r = (const float*)d_in[7];
    float* out = (float*)d_out;

    static bool attr_set = false;
    if (!attr_set) {
        cudaFuncSetAttribute(sage_gemm_mma,
                             cudaFuncAttributeMaxDynamicSharedMemorySize,
                             GEMM_SMEM_BYTES);
        attr_set = true;
    }

    float* agg_p;  cudaGetSymbolAddress((void**)&agg_p, g_agg);
    float* cnt_p;  cudaGetSymbolAddress((void**)&cnt_p, g_cnt);
    float* h1_p;   cudaGetSymbolAddress((void**)&h1_p, g_h1);

    const int agg4 = N_NODES * D / 4;

    // zero counts + layer-1 accumulator
    zero_kernel<<<64, 256>>>((float4*)cnt_p, N_NODES / 4);
    zero_kernel<<<2048, 256>>>((float4*)agg_p, agg4);

    // --- layer 1 ---
    scatter_kernel<<<2048, 256>>>(edge_index, node_emb, 1);
    sage_gemm_mma<<<148, 512, GEMM_SMEM_BYTES>>>(node_emb, w1_l, w1_r, b1_l,
                                                 h1_p, 1);

    // --- layer 2 ---
    zero_kernel<<<2048, 256>>>((float4*)agg_p, agg4);
    scatter_kernel<<<2048, 256>>>(edge_index, h1_p, 0);
    sage_gemm_mma<<<148, 512, GEMM_SMEM_BYTES>>>(h1_p, w2_l, w2_r, b2_l,
                                                 out, 0);

    (void)in_sizes; (void)n_in; (void)out_size;
}